// round 1
// baseline (speedup 1.0000x reference)
#include <cuda_runtime.h>
#include <math.h>

#define NTOK 1024
#define CDIM 64
#define BATCH 2
#define SS (NTOK*NTOK)
#define KSEL (SS/6)   /* 174762 */

// ---------------- device scratch (no allocations allowed) ----------------
__device__ float g_mean[BATCH*NTOK];
__device__ float g_std[BATCH*NTOK];
__device__ float g_E[BATCH*SS];
__device__ float g_Ch[BATCH*SS];
__device__ float g_Corr[BATCH*SS];
__device__ float g_L[BATCH*SS];     // logits -> attn (in place)
__device__ float g_W[BATCH*SS];     // weighted
__device__ unsigned g_hist[BATCH][256];
struct SelState { unsigned prefix, kneed, T, ct, idxT, tiecount; };
__device__ SelState g_sel[BATCH];
__device__ int g_ties[BATCH*SS];

// order-preserving float -> uint key
__device__ __forceinline__ unsigned fkey(float f) {
    unsigned u = __float_as_uint(f);
    return (u & 0x80000000u) ? ~u : (u | 0x80000000u);
}

// ---------------- row stats: mean + std (of centered row) ----------------
__global__ void row_stats(const float* __restrict__ x) {
    int warp = threadIdx.x >> 5, lane = threadIdx.x & 31;
    int row = blockIdx.x * 8 + warp;            // [0, BATCH*NTOK)
    const float* xr = x + (size_t)row * CDIM;
    float v0 = xr[lane], v1 = xr[lane + 32];
    float s = v0 + v1;
    #pragma unroll
    for (int o = 16; o; o >>= 1) s += __shfl_xor_sync(0xFFFFFFFFu, s, o);
    float mean = s * (1.0f / CDIM);
    float d0 = v0 - mean, d1 = v1 - mean;
    float ss = d0 * d0 + d1 * d1;
    #pragma unroll
    for (int o = 16; o; o >>= 1) ss += __shfl_xor_sync(0xFFFFFFFFu, ss, o);
    if (lane == 0) { g_mean[row] = mean; g_std[row] = sqrtf(ss); }
}

// ---------------- fused pairwise: euclidean, chebyshev, corrcoef ----------------
__global__ __launch_bounds__(256) void pairwise(const float* __restrict__ x) {
    __shared__ float xi[32][CDIM + 1];
    __shared__ float xj[32][CDIM + 1];
    __shared__ float smi[32], ssi[32], smj[32], ssj[32];
    int b = blockIdx.z;
    int i0 = blockIdx.y * 32, j0 = blockIdx.x * 32;
    const float* xb = x + (size_t)b * NTOK * CDIM;
    int tid = threadIdx.x;
    for (int l = tid; l < 32 * CDIM; l += 256) {
        int r = l >> 6, c = l & 63;
        xi[r][c] = xb[(size_t)(i0 + r) * CDIM + c];
        xj[r][c] = xb[(size_t)(j0 + r) * CDIM + c];
    }
    if (tid < 32)      { smi[tid] = g_mean[b*NTOK + i0 + tid]; ssi[tid] = g_std[b*NTOK + i0 + tid]; }
    else if (tid < 64) { int t = tid - 32; smj[t] = g_mean[b*NTOK + j0 + t]; ssj[t] = g_std[b*NTOK + j0 + t]; }
    __syncthreads();

    int tx = tid & 15, ty = tid >> 4;
    int r0 = ty * 2, r1 = ty * 2 + 1;
    int c0 = tx, c1 = tx + 16;

    float ssq[2][2] = {{0,0},{0,0}};
    float mx[2][2]  = {{0,0},{0,0}};
    float dt[2][2]  = {{0,0},{0,0}};
    float mi0 = smi[r0], mi1 = smi[r1], mj0 = smj[c0], mj1 = smj[c1];

    #pragma unroll 16
    for (int c = 0; c < CDIM; c++) {
        float a0 = xi[r0][c], a1 = xi[r1][c];
        float b0 = xj[c0][c], b1 = xj[c1][c];
        float ac0 = a0 - mi0, ac1 = a1 - mi1;
        float bc0 = b0 - mj0, bc1 = b1 - mj1;
        float d;
        d = a0 - b0; ssq[0][0] = fmaf(d,d,ssq[0][0]); mx[0][0] = fmaxf(mx[0][0], fabsf(d)); dt[0][0] = fmaf(ac0,bc0,dt[0][0]);
        d = a0 - b1; ssq[0][1] = fmaf(d,d,ssq[0][1]); mx[0][1] = fmaxf(mx[0][1], fabsf(d)); dt[0][1] = fmaf(ac0,bc1,dt[0][1]);
        d = a1 - b0; ssq[1][0] = fmaf(d,d,ssq[1][0]); mx[1][0] = fmaxf(mx[1][0], fabsf(d)); dt[1][0] = fmaf(ac1,bc0,dt[1][0]);
        d = a1 - b1; ssq[1][1] = fmaf(d,d,ssq[1][1]); mx[1][1] = fmaxf(mx[1][1], fabsf(d)); dt[1][1] = fmaf(ac1,bc1,dt[1][1]);
    }
    #pragma unroll
    for (int p = 0; p < 2; p++) {
        int I = i0 + r0 + p;
        float si = ssi[r0 + p];
        #pragma unroll
        for (int q = 0; q < 2; q++) {
            int J = j0 + ((q == 0) ? c0 : c1);
            size_t o = (size_t)b * SS + (size_t)I * NTOK + J;
            g_E[o]  = sqrtf(ssq[p][q]);
            g_Ch[o] = mx[p][q];
            float cr = dt[p][q] / (si * ssj[(q==0)?c0:c1]);
            g_Corr[o] = fminf(fmaxf(cr, -1.0f), 1.0f);
        }
    }
}

// ---------------- fp32 SGEMM NN: C = A*B (N=1024), batched via z ----------------
__global__ __launch_bounds__(256) void sgemm_nn(int which) {
    const float* A; const float* B; float* C;
    if (which == 0) { A = g_E; B = g_Ch;   C = g_L; }
    else            { A = g_L; B = g_Corr; C = g_W; }
    const int N = NTOK;
    int b = blockIdx.z;
    const float* Ab = A + (size_t)b * SS;
    const float* Bb = B + (size_t)b * SS;
    float* Cb = C + (size_t)b * SS;

    __shared__ float As[8][128];
    __shared__ float Bs[8][128];
    int tid = threadIdx.x;
    int tx = tid & 15, ty = tid >> 4;
    int rowBase = blockIdx.y * 128;
    int colBase = blockIdx.x * 128;
    int aRow = tid >> 1;
    int aSeg = (tid & 1) * 4;
    int bRow = tid >> 5;
    int bCol = (tid & 31) * 4;

    float acc[8][8];
    #pragma unroll
    for (int m = 0; m < 8; m++)
        #pragma unroll
        for (int n = 0; n < 8; n++) acc[m][n] = 0.0f;

    for (int k0 = 0; k0 < N; k0 += 8) {
        float4 a4 = *(const float4*)(Ab + (size_t)(rowBase + aRow) * N + k0 + aSeg);
        As[aSeg + 0][aRow] = a4.x; As[aSeg + 1][aRow] = a4.y;
        As[aSeg + 2][aRow] = a4.z; As[aSeg + 3][aRow] = a4.w;
        float4 b4 = *(const float4*)(Bb + (size_t)(k0 + bRow) * N + colBase + bCol);
        *(float4*)&Bs[bRow][bCol] = b4;
        __syncthreads();
        #pragma unroll
        for (int kk = 0; kk < 8; kk++) {
            float ar[8], br[8];
            #pragma unroll
            for (int m = 0; m < 8; m++) ar[m] = As[kk][ty * 8 + m];
            #pragma unroll
            for (int n = 0; n < 8; n++) br[n] = Bs[kk][tx * 8 + n];
            #pragma unroll
            for (int m = 0; m < 8; m++)
                #pragma unroll
                for (int n = 0; n < 8; n++)
                    acc[m][n] = fmaf(ar[m], br[n], acc[m][n]);
        }
        __syncthreads();
    }
    #pragma unroll
    for (int m = 0; m < 8; m++) {
        #pragma unroll
        for (int n4 = 0; n4 < 8; n4 += 4) {
            float4 v = make_float4(acc[m][n4], acc[m][n4+1], acc[m][n4+2], acc[m][n4+3]);
            *(float4*)(Cb + (size_t)(rowBase + ty*8 + m) * N + colBase + tx*8 + n4) = v;
        }
    }
}

// ---------------- row softmax of 0.125*L, in place ----------------
__global__ void softmax_rows() {
    int b = blockIdx.y, row = blockIdx.x;
    float* L = g_L + (size_t)b * SS + (size_t)row * NTOK;
    int tid = threadIdx.x;  // 256
    float v[4];
    #pragma unroll
    for (int i = 0; i < 4; i++) v[i] = L[tid + i * 256] * 0.125f;
    float m = fmaxf(fmaxf(v[0], v[1]), fmaxf(v[2], v[3]));
    __shared__ float red[256];
    red[tid] = m; __syncthreads();
    for (int s = 128; s; s >>= 1) { if (tid < s) red[tid] = fmaxf(red[tid], red[tid + s]); __syncthreads(); }
    m = red[0]; __syncthreads();
    float e[4], sm = 0.0f;
    #pragma unroll
    for (int i = 0; i < 4; i++) { e[i] = expf(v[i] - m); sm += e[i]; }
    red[tid] = sm; __syncthreads();
    for (int s = 128; s; s >>= 1) { if (tid < s) red[tid] += red[tid + s]; __syncthreads(); }
    sm = red[0];
    #pragma unroll
    for (int i = 0; i < 4; i++) L[tid + i * 256] = e[i] / sm;
}

// ---------------- top-k radix select ----------------
__global__ void sel_init() {
    int b = blockIdx.x;
    for (int i = threadIdx.x; i < 256; i += blockDim.x) g_hist[b][i] = 0;
    if (threadIdx.x == 0) {
        g_sel[b].prefix = 0; g_sel[b].kneed = KSEL; g_sel[b].T = 0;
        g_sel[b].ct = 0; g_sel[b].idxT = 0; g_sel[b].tiecount = 0;
    }
}

__global__ void sel_hist(int level) {
    int b = blockIdx.y;
    __shared__ unsigned h[256];
    for (int i = threadIdx.x; i < 256; i += blockDim.x) h[i] = 0;
    __syncthreads();
    unsigned prefix = g_sel[b].prefix;
    int shift = 24 - 8 * level;
    unsigned pmask = (level == 0) ? 0u : (0xFFFFFFFFu << (shift + 8));
    const float* W = g_W + (size_t)b * SS;
    for (int i = blockIdx.x * blockDim.x + threadIdx.x; i < SS; i += gridDim.x * blockDim.x) {
        unsigned u = fkey(W[i]);
        if ((u & pmask) == prefix) atomicAdd(&h[(u >> shift) & 255], 1u);
    }
    __syncthreads();
    for (int i = threadIdx.x; i < 256; i += blockDim.x)
        if (h[i]) atomicAdd(&g_hist[b][i], h[i]);
}

__global__ void sel_scan(int level) {
    int b = blockIdx.x;
    SelState& st = g_sel[b];
    int shift = 24 - 8 * level;
    unsigned kneed = st.kneed;
    int sel = 0; unsigned cnt = 0;
    for (int bin = 255; bin >= 0; bin--) {
        unsigned c = g_hist[b][bin];
        if (kneed <= c) { sel = bin; cnt = c; break; }
        kneed -= c;
    }
    st.prefix |= ((unsigned)sel) << shift;
    st.kneed = kneed;
    if (level == 3) { st.T = st.prefix; st.ct = cnt; }
    for (int i = 0; i < 256; i++) g_hist[b][i] = 0;
}

__global__ void sel_gather() {
    int b = blockIdx.y;
    unsigned T = g_sel[b].T;
    const float* W = g_W + (size_t)b * SS;
    for (int i = blockIdx.x * blockDim.x + threadIdx.x; i < SS; i += gridDim.x * blockDim.x) {
        if (fkey(W[i]) == T) {
            unsigned pos = atomicAdd(&g_sel[b].tiecount, 1u);
            g_ties[(size_t)b * SS + pos] = i;
        }
    }
}

__global__ void sel_idx() {
    int b = blockIdx.x;
    __shared__ unsigned cnt;
    SelState& st = g_sel[b];
    unsigned ct = st.ct, need = st.kneed;
    if (need >= ct) { if (threadIdx.x == 0) st.idxT = 0; return; }
    const int* ties = g_ties + (size_t)b * SS;
    unsigned lo = 0, hi = SS - 1;  // find max t with count(idx >= t) >= need
    for (int iter = 0; iter < 22; iter++) {
        if (lo >= hi) break;
        unsigned mid = (lo + hi + 1u) >> 1;
        if (threadIdx.x == 0) cnt = 0;
        __syncthreads();
        unsigned local = 0;
        for (unsigned i = threadIdx.x; i < ct; i += blockDim.x)
            local += (ties[i] >= (int)mid) ? 1u : 0u;
        if (local) atomicAdd(&cnt, local);
        __syncthreads();
        if (cnt >= need) lo = mid; else hi = mid - 1;
        __syncthreads();
    }
    if (threadIdx.x == 0) st.idxT = lo;
}

__global__ void mask_write(float* __restrict__ out) {
    int b = blockIdx.y;
    int idx = blockIdx.x * blockDim.x + threadIdx.x;
    unsigned T = g_sel[b].T;
    unsigned idxT = g_sel[b].idxT;
    unsigned u = fkey(g_W[(size_t)b * SS + idx]);
    float v = (u > T || (u == T && (unsigned)idx >= idxT)) ? 1.0f : 0.0f;
    out[(size_t)b * SS + idx] = v;
}

// ---------------- launcher ----------------
extern "C" void kernel_launch(void* const* d_in, const int* in_sizes, int n_in,
                              void* d_out, int out_size) {
    const float* x = (const float*)d_in[0];
    float* out = (float*)d_out;

    row_stats<<<(BATCH * NTOK) / 8, 256>>>(x);
    pairwise<<<dim3(32, 32, BATCH), 256>>>(x);
    sgemm_nn<<<dim3(8, 8, BATCH), 256>>>(0);
    softmax_rows<<<dim3(NTOK, BATCH), 256>>>();
    sgemm_nn<<<dim3(8, 8, BATCH), 256>>>(1);

    sel_init<<<BATCH, 256>>>();
    for (int level = 0; level < 4; level++) {
        sel_hist<<<dim3(128, BATCH), 256>>>(level);
        sel_scan<<<BATCH, 1>>>(level);
    }
    sel_gather<<<dim3(128, BATCH), 256>>>();
    sel_idx<<<BATCH, 1024>>>();
    mask_write<<<dim3(NTOK, BATCH), 1024>>>(out);
}

// round 2
// speedup vs baseline: 1.0491x; 1.0491x over previous
#include <cuda_runtime.h>
#include <math.h>

#define NTOK 1024
#define CDIM 64
#define BATCH 2
#define SS (NTOK*NTOK)
#define KSEL (SS/6)   /* 174762 */

// ---------------- device scratch (no allocations allowed) ----------------
__device__ float g_mean[BATCH*NTOK];
__device__ float g_std[BATCH*NTOK];
__device__ float g_E[BATCH*SS];
__device__ float g_Ch[BATCH*SS];
__device__ float g_Corr[BATCH*SS];
__device__ float g_L[BATCH*SS];     // logits -> attn (in place)
__device__ float g_W[BATCH*SS];     // weighted
__device__ unsigned g_hist[BATCH][256];
struct SelState { unsigned prefix, kneed, T, ct, idxT, tiecount; };
__device__ SelState g_sel[BATCH];
__device__ int g_ties[BATCH*SS];

// order-preserving float -> uint key
__device__ __forceinline__ unsigned fkey(float f) {
    unsigned u = __float_as_uint(f);
    return (u & 0x80000000u) ? ~u : (u | 0x80000000u);
}

// ---------------- packed f32x2 helpers (FFMA2 path, sm_103a) ----------------
__device__ __forceinline__ unsigned long long pack_dup(float v) {
    unsigned long long r;
    asm("mov.b64 %0, {%1, %1};" : "=l"(r) : "f"(v));
    return r;
}
__device__ __forceinline__ unsigned long long pack2(float lo, float hi) {
    unsigned long long r;
    asm("mov.b64 %0, {%1, %2};" : "=l"(r) : "f"(lo), "f"(hi));
    return r;
}
#define FMA2(acc, a, b) \
    asm("fma.rn.f32x2 %0, %1, %2, %0;" : "+l"(acc) : "l"(a), "l"(b))

// ---------------- row stats: mean + std (of centered row) ----------------
__global__ void row_stats(const float* __restrict__ x) {
    int warp = threadIdx.x >> 5, lane = threadIdx.x & 31;
    int row = blockIdx.x * 8 + warp;            // [0, BATCH*NTOK)
    const float* xr = x + (size_t)row * CDIM;
    float v0 = xr[lane], v1 = xr[lane + 32];
    float s = v0 + v1;
    #pragma unroll
    for (int o = 16; o; o >>= 1) s += __shfl_xor_sync(0xFFFFFFFFu, s, o);
    float mean = s * (1.0f / CDIM);
    float d0 = v0 - mean, d1 = v1 - mean;
    float ss = d0 * d0 + d1 * d1;
    #pragma unroll
    for (int o = 16; o; o >>= 1) ss += __shfl_xor_sync(0xFFFFFFFFu, ss, o);
    if (lane == 0) { g_mean[row] = mean; g_std[row] = sqrtf(ss); }
}

// ---------------- fused pairwise: euclidean, chebyshev, corrcoef ----------------
__global__ __launch_bounds__(256) void pairwise(const float* __restrict__ x) {
    __shared__ float xi[32][CDIM + 1];
    __shared__ float xj[32][CDIM + 1];
    __shared__ float smi[32], ssi[32], smj[32], ssj[32];
    int b = blockIdx.z;
    int i0 = blockIdx.y * 32, j0 = blockIdx.x * 32;
    const float* xb = x + (size_t)b * NTOK * CDIM;
    int tid = threadIdx.x;
    for (int l = tid; l < 32 * CDIM; l += 256) {
        int r = l >> 6, c = l & 63;
        xi[r][c] = xb[(size_t)(i0 + r) * CDIM + c];
        xj[r][c] = xb[(size_t)(j0 + r) * CDIM + c];
    }
    if (tid < 32)      { smi[tid] = g_mean[b*NTOK + i0 + tid]; ssi[tid] = g_std[b*NTOK + i0 + tid]; }
    else if (tid < 64) { int t = tid - 32; smj[t] = g_mean[b*NTOK + j0 + t]; ssj[t] = g_std[b*NTOK + j0 + t]; }
    __syncthreads();

    int tx = tid & 15, ty = tid >> 4;
    int r0 = ty * 2, r1 = ty * 2 + 1;
    int c0 = tx, c1 = tx + 16;

    float ssq[2][2] = {{0,0},{0,0}};
    float mx[2][2]  = {{0,0},{0,0}};
    float dt[2][2]  = {{0,0},{0,0}};
    float mi0 = smi[r0], mi1 = smi[r1], mj0 = smj[c0], mj1 = smj[c1];

    #pragma unroll 16
    for (int c = 0; c < CDIM; c++) {
        float a0 = xi[r0][c], a1 = xi[r1][c];
        float b0 = xj[c0][c], b1 = xj[c1][c];
        float ac0 = a0 - mi0, ac1 = a1 - mi1;
        float bc0 = b0 - mj0, bc1 = b1 - mj1;
        float d;
        d = a0 - b0; ssq[0][0] = fmaf(d,d,ssq[0][0]); mx[0][0] = fmaxf(mx[0][0], fabsf(d)); dt[0][0] = fmaf(ac0,bc0,dt[0][0]);
        d = a0 - b1; ssq[0][1] = fmaf(d,d,ssq[0][1]); mx[0][1] = fmaxf(mx[0][1], fabsf(d)); dt[0][1] = fmaf(ac0,bc1,dt[0][1]);
        d = a1 - b0; ssq[1][0] = fmaf(d,d,ssq[1][0]); mx[1][0] = fmaxf(mx[1][0], fabsf(d)); dt[1][0] = fmaf(ac1,bc0,dt[1][0]);
        d = a1 - b1; ssq[1][1] = fmaf(d,d,ssq[1][1]); mx[1][1] = fmaxf(mx[1][1], fabsf(d)); dt[1][1] = fmaf(ac1,bc1,dt[1][1]);
    }
    #pragma unroll
    for (int p = 0; p < 2; p++) {
        int I = i0 + r0 + p;
        float si = ssi[r0 + p];
        #pragma unroll
        for (int q = 0; q < 2; q++) {
            int J = j0 + ((q == 0) ? c0 : c1);
            size_t o = (size_t)b * SS + (size_t)I * NTOK + J;
            g_E[o]  = sqrtf(ssq[p][q]);
            g_Ch[o] = mx[p][q];
            float cr = dt[p][q] / (si * ssj[(q==0)?c0:c1]);
            g_Corr[o] = fminf(fmaxf(cr, -1.0f), 1.0f);
        }
    }
}

// ---------------- fp32 SGEMM NN via packed FFMA2: C = A*B (N=1024) ----------------
__global__ __launch_bounds__(256) void sgemm_nn(int which) {
    const float* A; const float* B; float* C;
    if (which == 0) { A = g_E; B = g_Ch;   C = g_L; }
    else            { A = g_L; B = g_Corr; C = g_W; }
    const int N = NTOK;
    int b = blockIdx.z;
    const float* Ab = A + (size_t)b * SS;
    const float* Bb = B + (size_t)b * SS;
    float* Cb = C + (size_t)b * SS;

    __shared__ float As[8][128];
    __shared__ float Bs[8][128];
    int tid = threadIdx.x;
    int tx = tid & 15, ty = tid >> 4;
    int rowBase = blockIdx.y * 128;
    int colBase = blockIdx.x * 128;
    int aRow = tid >> 1;
    int aSeg = (tid & 1) * 4;
    int bRow = tid >> 5;
    int bCol = (tid & 31) * 4;

    // packed accumulators: acc2[m][n2] = {C[m][2*n2], C[m][2*n2+1]}
    unsigned long long acc2[8][4];
    #pragma unroll
    for (int m = 0; m < 8; m++)
        #pragma unroll
        for (int n = 0; n < 4; n++) acc2[m][n] = 0ull;

    for (int k0 = 0; k0 < N; k0 += 8) {
        float4 a4 = *(const float4*)(Ab + (size_t)(rowBase + aRow) * N + k0 + aSeg);
        As[aSeg + 0][aRow] = a4.x; As[aSeg + 1][aRow] = a4.y;
        As[aSeg + 2][aRow] = a4.z; As[aSeg + 3][aRow] = a4.w;
        float4 b4 = *(const float4*)(Bb + (size_t)(k0 + bRow) * N + colBase + bCol);
        *(float4*)&Bs[bRow][bCol] = b4;
        __syncthreads();
        #pragma unroll
        for (int kk = 0; kk < 8; kk++) {
            float4 alo = *(const float4*)&As[kk][ty * 8];
            float4 ahi = *(const float4*)&As[kk][ty * 8 + 4];
            float4 blo = *(const float4*)&Bs[kk][tx * 8];
            float4 bhi = *(const float4*)&Bs[kk][tx * 8 + 4];
            unsigned long long a2[8], b2[4];
            a2[0] = pack_dup(alo.x); a2[1] = pack_dup(alo.y);
            a2[2] = pack_dup(alo.z); a2[3] = pack_dup(alo.w);
            a2[4] = pack_dup(ahi.x); a2[5] = pack_dup(ahi.y);
            a2[6] = pack_dup(ahi.z); a2[7] = pack_dup(ahi.w);
            b2[0] = pack2(blo.x, blo.y); b2[1] = pack2(blo.z, blo.w);
            b2[2] = pack2(bhi.x, bhi.y); b2[3] = pack2(bhi.z, bhi.w);
            #pragma unroll
            for (int m = 0; m < 8; m++)
                #pragma unroll
                for (int n = 0; n < 4; n++)
                    FMA2(acc2[m][n], a2[m], b2[n]);
        }
        __syncthreads();
    }
    #pragma unroll
    for (int m = 0; m < 8; m++) {
        ulonglong2 v0, v1;
        v0.x = acc2[m][0]; v0.y = acc2[m][1];
        v1.x = acc2[m][2]; v1.y = acc2[m][3];
        *(ulonglong2*)(Cb + (size_t)(rowBase + ty*8 + m) * N + colBase + tx*8)     = v0;
        *(ulonglong2*)(Cb + (size_t)(rowBase + ty*8 + m) * N + colBase + tx*8 + 4) = v1;
    }
}

// ---------------- row softmax of 0.125*L, in place ----------------
__global__ void softmax_rows() {
    int b = blockIdx.y, row = blockIdx.x;
    float* L = g_L + (size_t)b * SS + (size_t)row * NTOK;
    int tid = threadIdx.x;  // 256
    float v[4];
    #pragma unroll
    for (int i = 0; i < 4; i++) v[i] = L[tid + i * 256] * 0.125f;
    float m = fmaxf(fmaxf(v[0], v[1]), fmaxf(v[2], v[3]));
    __shared__ float red[256];
    red[tid] = m; __syncthreads();
    for (int s = 128; s; s >>= 1) { if (tid < s) red[tid] = fmaxf(red[tid], red[tid + s]); __syncthreads(); }
    m = red[0]; __syncthreads();
    float e[4], sm = 0.0f;
    #pragma unroll
    for (int i = 0; i < 4; i++) { e[i] = expf(v[i] - m); sm += e[i]; }
    red[tid] = sm; __syncthreads();
    for (int s = 128; s; s >>= 1) { if (tid < s) red[tid] += red[tid + s]; __syncthreads(); }
    sm = red[0];
    #pragma unroll
    for (int i = 0; i < 4; i++) L[tid + i * 256] = e[i] / sm;
}

// ---------------- top-k radix select ----------------
__global__ void sel_init() {
    int b = blockIdx.x;
    for (int i = threadIdx.x; i < 256; i += blockDim.x) g_hist[b][i] = 0;
    if (threadIdx.x == 0) {
        g_sel[b].prefix = 0; g_sel[b].kneed = KSEL; g_sel[b].T = 0;
        g_sel[b].ct = 0; g_sel[b].idxT = 0; g_sel[b].tiecount = 0;
    }
}

__global__ void sel_hist(int level) {
    int b = blockIdx.y;
    __shared__ unsigned h[256];
    for (int i = threadIdx.x; i < 256; i += blockDim.x) h[i] = 0;
    __syncthreads();
    unsigned prefix = g_sel[b].prefix;
    int shift = 24 - 8 * level;
    unsigned pmask = (level == 0) ? 0u : (0xFFFFFFFFu << (shift + 8));
    const float* W = g_W + (size_t)b * SS;
    for (int i = blockIdx.x * blockDim.x + threadIdx.x; i < SS; i += gridDim.x * blockDim.x) {
        unsigned u = fkey(W[i]);
        if ((u & pmask) == prefix) atomicAdd(&h[(u >> shift) & 255], 1u);
    }
    __syncthreads();
    for (int i = threadIdx.x; i < 256; i += blockDim.x)
        if (h[i]) atomicAdd(&g_hist[b][i], h[i]);
}

__global__ void sel_scan(int level) {
    int b = blockIdx.x;
    SelState& st = g_sel[b];
    int shift = 24 - 8 * level;
    unsigned kneed = st.kneed;
    int sel = 0; unsigned cnt = 0;
    for (int bin = 255; bin >= 0; bin--) {
        unsigned c = g_hist[b][bin];
        if (kneed <= c) { sel = bin; cnt = c; break; }
        kneed -= c;
    }
    st.prefix |= ((unsigned)sel) << shift;
    st.kneed = kneed;
    if (level == 3) { st.T = st.prefix; st.ct = cnt; }
    for (int i = 0; i < 256; i++) g_hist[b][i] = 0;
}

__global__ void sel_gather() {
    int b = blockIdx.y;
    unsigned T = g_sel[b].T;
    const float* W = g_W + (size_t)b * SS;
    for (int i = blockIdx.x * blockDim.x + threadIdx.x; i < SS; i += gridDim.x * blockDim.x) {
        if (fkey(W[i]) == T) {
            unsigned pos = atomicAdd(&g_sel[b].tiecount, 1u);
            g_ties[(size_t)b * SS + pos] = i;
        }
    }
}

__global__ void sel_idx() {
    int b = blockIdx.x;
    __shared__ unsigned cnt;
    SelState& st = g_sel[b];
    unsigned ct = st.ct, need = st.kneed;
    if (need >= ct) { if (threadIdx.x == 0) st.idxT = 0; return; }
    const int* ties = g_ties + (size_t)b * SS;
    unsigned lo = 0, hi = SS - 1;  // find max t with count(idx >= t) >= need
    for (int iter = 0; iter < 22; iter++) {
        if (lo >= hi) break;
        unsigned mid = (lo + hi + 1u) >> 1;
        if (threadIdx.x == 0) cnt = 0;
        __syncthreads();
        unsigned local = 0;
        for (unsigned i = threadIdx.x; i < ct; i += blockDim.x)
            local += (ties[i] >= (int)mid) ? 1u : 0u;
        if (local) atomicAdd(&cnt, local);
        __syncthreads();
        if (cnt >= need) lo = mid; else hi = mid - 1;
        __syncthreads();
    }
    if (threadIdx.x == 0) st.idxT = lo;
}

__global__ void mask_write(float* __restrict__ out) {
    int b = blockIdx.y;
    int idx = blockIdx.x * blockDim.x + threadIdx.x;
    unsigned T = g_sel[b].T;
    unsigned idxT = g_sel[b].idxT;
    unsigned u = fkey(g_W[(size_t)b * SS + idx]);
    float v = (u > T || (u == T && (unsigned)idx >= idxT)) ? 1.0f : 0.0f;
    out[(size_t)b * SS + idx] = v;
}

// ---------------- launcher ----------------
extern "C" void kernel_launch(void* const* d_in, const int* in_sizes, int n_in,
                              void* d_out, int out_size) {
    const float* x = (const float*)d_in[0];
    float* out = (float*)d_out;

    row_stats<<<(BATCH * NTOK) / 8, 256>>>(x);
    pairwise<<<dim3(32, 32, BATCH), 256>>>(x);
    sgemm_nn<<<dim3(8, 8, BATCH), 256>>>(0);
    softmax_rows<<<dim3(NTOK, BATCH), 256>>>();
    sgemm_nn<<<dim3(8, 8, BATCH), 256>>>(1);

    sel_init<<<BATCH, 256>>>();
    for (int level = 0; level < 4; level++) {
        sel_hist<<<dim3(128, BATCH), 256>>>(level);
        sel_scan<<<BATCH, 1>>>(level);
    }
    sel_gather<<<dim3(128, BATCH), 256>>>();
    sel_idx<<<BATCH, 1024>>>();
    mask_write<<<dim3(NTOK, BATCH), 1024>>>(out);
}

// round 3
// speedup vs baseline: 1.2468x; 1.1884x over previous
#include <cuda_runtime.h>
#include <math.h>

#define NTOK 1024
#define CDIM 64
#define BATCH 2
#define SS (NTOK*NTOK)
#define KSEL (SS/6)   /* 174762 */

// ---------------- device scratch (no allocations allowed) ----------------
__device__ float g_mean[BATCH*NTOK];
__device__ float g_std[BATCH*NTOK];
__device__ float g_E[BATCH*SS];
__device__ float g_Ch[BATCH*SS];
__device__ float g_Corr[BATCH*SS];
__device__ float g_L[BATCH*SS];     // logits -> attn (in place)
__device__ float g_W[BATCH*SS];     // weighted
__device__ unsigned g_hist[BATCH][256];
struct SelState { unsigned prefix, kneed, T, ct, idxT, tiecount; };
__device__ SelState g_sel[BATCH];
__device__ int g_ties[BATCH*SS];

// order-preserving float -> uint key
__device__ __forceinline__ unsigned fkey(float f) {
    unsigned u = __float_as_uint(f);
    return (u & 0x80000000u) ? ~u : (u | 0x80000000u);
}

// ---------------- packed f32x2 helpers (FFMA2 path, sm_103a) ----------------
__device__ __forceinline__ unsigned long long pack_dup(float v) {
    unsigned long long r;
    asm("mov.b64 %0, {%1, %1};" : "=l"(r) : "f"(v));
    return r;
}
#define FMA2(acc, a, b) \
    asm("fma.rn.f32x2 %0, %1, %2, %0;" : "+l"(acc) : "l"(a), "l"(b))

union F4U { float4 f; unsigned long long u[2]; };

// ---------------- row stats: mean + std (of centered row) ----------------
__global__ void row_stats(const float* __restrict__ x) {
    int warp = threadIdx.x >> 5, lane = threadIdx.x & 31;
    int row = blockIdx.x * 8 + warp;            // [0, BATCH*NTOK)
    const float* xr = x + (size_t)row * CDIM;
    float v0 = xr[lane], v1 = xr[lane + 32];
    float s = v0 + v1;
    #pragma unroll
    for (int o = 16; o; o >>= 1) s += __shfl_xor_sync(0xFFFFFFFFu, s, o);
    float mean = s * (1.0f / CDIM);
    float d0 = v0 - mean, d1 = v1 - mean;
    float ss = d0 * d0 + d1 * d1;
    #pragma unroll
    for (int o = 16; o; o >>= 1) ss += __shfl_xor_sync(0xFFFFFFFFu, ss, o);
    if (lane == 0) { g_mean[row] = mean; g_std[row] = sqrtf(ss); }
}

// ---------------- fused pairwise: euclidean, chebyshev, corrcoef ----------------
__global__ __launch_bounds__(256) void pairwise(const float* __restrict__ x) {
    __shared__ float xi[32][CDIM + 1];
    __shared__ float xj[32][CDIM + 1];
    __shared__ float smi[32], ssi[32], smj[32], ssj[32];
    int b = blockIdx.z;
    int i0 = blockIdx.y * 32, j0 = blockIdx.x * 32;
    const float* xb = x + (size_t)b * NTOK * CDIM;
    int tid = threadIdx.x;
    for (int l = tid; l < 32 * CDIM; l += 256) {
        int r = l >> 6, c = l & 63;
        xi[r][c] = xb[(size_t)(i0 + r) * CDIM + c];
        xj[r][c] = xb[(size_t)(j0 + r) * CDIM + c];
    }
    if (tid < 32)      { smi[tid] = g_mean[b*NTOK + i0 + tid]; ssi[tid] = g_std[b*NTOK + i0 + tid]; }
    else if (tid < 64) { int t = tid - 32; smj[t] = g_mean[b*NTOK + j0 + t]; ssj[t] = g_std[b*NTOK + j0 + t]; }
    __syncthreads();

    int tx = tid & 15, ty = tid >> 4;
    int r0 = ty * 2, r1 = ty * 2 + 1;
    int c0 = tx, c1 = tx + 16;

    float ssq[2][2] = {{0,0},{0,0}};
    float mx[2][2]  = {{0,0},{0,0}};
    float dt[2][2]  = {{0,0},{0,0}};
    float mi0 = smi[r0], mi1 = smi[r1], mj0 = smj[c0], mj1 = smj[c1];

    #pragma unroll 16
    for (int c = 0; c < CDIM; c++) {
        float a0 = xi[r0][c], a1 = xi[r1][c];
        float b0 = xj[c0][c], b1 = xj[c1][c];
        float ac0 = a0 - mi0, ac1 = a1 - mi1;
        float bc0 = b0 - mj0, bc1 = b1 - mj1;
        float d;
        d = a0 - b0; ssq[0][0] = fmaf(d,d,ssq[0][0]); mx[0][0] = fmaxf(mx[0][0], fabsf(d)); dt[0][0] = fmaf(ac0,bc0,dt[0][0]);
        d = a0 - b1; ssq[0][1] = fmaf(d,d,ssq[0][1]); mx[0][1] = fmaxf(mx[0][1], fabsf(d)); dt[0][1] = fmaf(ac0,bc1,dt[0][1]);
        d = a1 - b0; ssq[1][0] = fmaf(d,d,ssq[1][0]); mx[1][0] = fmaxf(mx[1][0], fabsf(d)); dt[1][0] = fmaf(ac1,bc0,dt[1][0]);
        d = a1 - b1; ssq[1][1] = fmaf(d,d,ssq[1][1]); mx[1][1] = fmaxf(mx[1][1], fabsf(d)); dt[1][1] = fmaf(ac1,bc1,dt[1][1]);
    }
    #pragma unroll
    for (int p = 0; p < 2; p++) {
        int I = i0 + r0 + p;
        float si = ssi[r0 + p];
        #pragma unroll
        for (int q = 0; q < 2; q++) {
            int J = j0 + ((q == 0) ? c0 : c1);
            size_t o = (size_t)b * SS + (size_t)I * NTOK + J;
            g_E[o]  = sqrtf(ssq[p][q]);
            g_Ch[o] = mx[p][q];
            float cr = dt[p][q] / (si * ssj[(q==0)?c0:c1]);
            g_Corr[o] = fminf(fmaxf(cr, -1.0f), 1.0f);
        }
    }
}

// ---- fp32 SGEMM NN, double-buffered k-tile 16, FFMA2 mainloop ----
__global__ __launch_bounds__(256) void sgemm_nn(int which) {
    const float* A; const float* B; float* C;
    if (which == 0) { A = g_E; B = g_Ch;   C = g_L; }
    else            { A = g_L; B = g_Corr; C = g_W; }
    const int N = NTOK;
    int b = blockIdx.z;
    const float* Ab = A + (size_t)b * SS;
    const float* Bb = B + (size_t)b * SS;
    float* Cb = C + (size_t)b * SS;

    __shared__ float As[2][16][128];
    __shared__ float Bs[2][16][128];
    int tid = threadIdx.x;
    int rowBase = blockIdx.y * 128;
    int colBase = blockIdx.x * 128;

    // LDG mapping: A tile 128 rows x 16 k -> thread loads row=tid>>1, k half (tid&1)*8
    int aRow = tid >> 1, aK = (tid & 1) * 8;
    // B tile 16 k x 128 cols -> thread loads krow=tid>>4, 8 cols at (tid&15)*8
    int bK = tid >> 4, bC = (tid & 15) * 8;

    const float* Aptr = Ab + (size_t)(rowBase + aRow) * N + aK;
    const float* Bptr = Bb + (size_t)bK * N + colBase + bC;

    float4 pa0 = *(const float4*)(Aptr);
    float4 pa1 = *(const float4*)(Aptr + 4);
    float4 pb0 = *(const float4*)(Bptr);
    float4 pb1 = *(const float4*)(Bptr + 4);

    // stage 0 store
    {
        As[0][aK+0][aRow] = pa0.x; As[0][aK+1][aRow] = pa0.y;
        As[0][aK+2][aRow] = pa0.z; As[0][aK+3][aRow] = pa0.w;
        As[0][aK+4][aRow] = pa1.x; As[0][aK+5][aRow] = pa1.y;
        As[0][aK+6][aRow] = pa1.z; As[0][aK+7][aRow] = pa1.w;
        *(float4*)&Bs[0][bK][bC]     = pb0;
        *(float4*)&Bs[0][bK][bC + 4] = pb1;
    }
    __syncthreads();

    int tx = tid & 15, ty = tid >> 4;

    unsigned long long acc2[8][4];
    #pragma unroll
    for (int m = 0; m < 8; m++)
        #pragma unroll
        for (int n = 0; n < 4; n++) acc2[m][n] = 0ull;

    const int NTILE = NTOK / 16;  // 64
    for (int t = 0; t < NTILE; t++) {
        int cur = t & 1;
        if (t < NTILE - 1) {
            int k0 = (t + 1) * 16;
            pa0 = *(const float4*)(Aptr + k0);
            pa1 = *(const float4*)(Aptr + k0 + 4);
            pb0 = *(const float4*)(Bptr + (size_t)k0 * N);
            pb1 = *(const float4*)(Bptr + (size_t)k0 * N + 4);
        }
        #pragma unroll
        for (int kk = 0; kk < 16; kk++) {
            F4U alo, ahi, blo, bhi;
            alo.f = *(const float4*)&As[cur][kk][ty * 8];
            ahi.f = *(const float4*)&As[cur][kk][ty * 8 + 4];
            blo.f = *(const float4*)&Bs[cur][kk][tx * 8];
            bhi.f = *(const float4*)&Bs[cur][kk][tx * 8 + 4];
            unsigned long long a2[8];
            a2[0] = pack_dup(alo.f.x); a2[1] = pack_dup(alo.f.y);
            a2[2] = pack_dup(alo.f.z); a2[3] = pack_dup(alo.f.w);
            a2[4] = pack_dup(ahi.f.x); a2[5] = pack_dup(ahi.f.y);
            a2[6] = pack_dup(ahi.f.z); a2[7] = pack_dup(ahi.f.w);
            unsigned long long b2[4];
            b2[0] = blo.u[0]; b2[1] = blo.u[1];
            b2[2] = bhi.u[0]; b2[3] = bhi.u[1];
            #pragma unroll
            for (int m = 0; m < 8; m++) {
                FMA2(acc2[m][0], a2[m], b2[0]);
                FMA2(acc2[m][1], a2[m], b2[1]);
                FMA2(acc2[m][2], a2[m], b2[2]);
                FMA2(acc2[m][3], a2[m], b2[3]);
            }
        }
        if (t < NTILE - 1) {
            int nxt = cur ^ 1;
            As[nxt][aK+0][aRow] = pa0.x; As[nxt][aK+1][aRow] = pa0.y;
            As[nxt][aK+2][aRow] = pa0.z; As[nxt][aK+3][aRow] = pa0.w;
            As[nxt][aK+4][aRow] = pa1.x; As[nxt][aK+5][aRow] = pa1.y;
            As[nxt][aK+6][aRow] = pa1.z; As[nxt][aK+7][aRow] = pa1.w;
            *(float4*)&Bs[nxt][bK][bC]     = pb0;
            *(float4*)&Bs[nxt][bK][bC + 4] = pb1;
        }
        __syncthreads();
    }

    #pragma unroll
    for (int m = 0; m < 8; m++) {
        ulonglong2 v0, v1;
        v0.x = acc2[m][0]; v0.y = acc2[m][1];
        v1.x = acc2[m][2]; v1.y = acc2[m][3];
        *(ulonglong2*)(Cb + (size_t)(rowBase + ty*8 + m) * N + colBase + tx*8)     = v0;
        *(ulonglong2*)(Cb + (size_t)(rowBase + ty*8 + m) * N + colBase + tx*8 + 4) = v1;
    }
}

// ---------------- row softmax of 0.125*L, in place ----------------
__global__ void softmax_rows() {
    int b = blockIdx.y, row = blockIdx.x;
    float* L = g_L + (size_t)b * SS + (size_t)row * NTOK;
    int tid = threadIdx.x;  // 256
    float v[4];
    #pragma unroll
    for (int i = 0; i < 4; i++) v[i] = L[tid + i * 256] * 0.125f;
    float m = fmaxf(fmaxf(v[0], v[1]), fmaxf(v[2], v[3]));
    __shared__ float red[256];
    red[tid] = m; __syncthreads();
    for (int s = 128; s; s >>= 1) { if (tid < s) red[tid] = fmaxf(red[tid], red[tid + s]); __syncthreads(); }
    m = red[0]; __syncthreads();
    float e[4], sm = 0.0f;
    #pragma unroll
    for (int i = 0; i < 4; i++) { e[i] = expf(v[i] - m); sm += e[i]; }
    red[tid] = sm; __syncthreads();
    for (int s = 128; s; s >>= 1) { if (tid < s) red[tid] += red[tid + s]; __syncthreads(); }
    sm = red[0];
    #pragma unroll
    for (int i = 0; i < 4; i++) L[tid + i * 256] = e[i] / sm;
}

// ---------------- top-k radix select ----------------
__global__ void sel_init() {
    int b = blockIdx.x;
    for (int i = threadIdx.x; i < 256; i += blockDim.x) g_hist[b][i] = 0;
    if (threadIdx.x == 0) {
        g_sel[b].prefix = 0; g_sel[b].kneed = KSEL; g_sel[b].T = 0;
        g_sel[b].ct = 0; g_sel[b].idxT = 0; g_sel[b].tiecount = 0;
    }
}

__global__ void sel_hist(int level) {
    int b = blockIdx.y;
    __shared__ unsigned h[256];
    for (int i = threadIdx.x; i < 256; i += blockDim.x) h[i] = 0;
    __syncthreads();
    unsigned prefix = g_sel[b].prefix;
    int shift = 24 - 8 * level;
    unsigned pmask = (level == 0) ? 0u : (0xFFFFFFFFu << (shift + 8));
    const float* W = g_W + (size_t)b * SS;
    for (int i = blockIdx.x * blockDim.x + threadIdx.x; i < SS; i += gridDim.x * blockDim.x) {
        unsigned u = fkey(W[i]);
        if ((u & pmask) == prefix) atomicAdd(&h[(u >> shift) & 255], 1u);
    }
    __syncthreads();
    for (int i = threadIdx.x; i < 256; i += blockDim.x)
        if (h[i]) atomicAdd(&g_hist[b][i], h[i]);
}

__global__ void sel_scan(int level) {
    int b = blockIdx.x;
    SelState& st = g_sel[b];
    int shift = 24 - 8 * level;
    unsigned kneed = st.kneed;
    int sel = 0; unsigned cnt = 0;
    for (int bin = 255; bin >= 0; bin--) {
        unsigned c = g_hist[b][bin];
        if (kneed <= c) { sel = bin; cnt = c; break; }
        kneed -= c;
    }
    st.prefix |= ((unsigned)sel) << shift;
    st.kneed = kneed;
    if (level == 3) { st.T = st.prefix; st.ct = cnt; }
    for (int i = 0; i < 256; i++) g_hist[b][i] = 0;
}

__global__ void sel_gather() {
    int b = blockIdx.y;
    unsigned T = g_sel[b].T;
    const float* W = g_W + (size_t)b * SS;
    for (int i = blockIdx.x * blockDim.x + threadIdx.x; i < SS; i += gridDim.x * blockDim.x) {
        if (fkey(W[i]) == T) {
            unsigned pos = atomicAdd(&g_sel[b].tiecount, 1u);
            g_ties[(size_t)b * SS + pos] = i;
        }
    }
}

__global__ void sel_idx() {
    int b = blockIdx.x;
    __shared__ unsigned cnt;
    SelState& st = g_sel[b];
    unsigned ct = st.ct, need = st.kneed;
    if (need >= ct) { if (threadIdx.x == 0) st.idxT = 0; return; }
    const int* ties = g_ties + (size_t)b * SS;
    unsigned lo = 0, hi = SS - 1;  // find max t with count(idx >= t) >= need
    for (int iter = 0; iter < 22; iter++) {
        if (lo >= hi) break;
        unsigned mid = (lo + hi + 1u) >> 1;
        if (threadIdx.x == 0) cnt = 0;
        __syncthreads();
        unsigned local = 0;
        for (unsigned i = threadIdx.x; i < ct; i += blockDim.x)
            local += (ties[i] >= (int)mid) ? 1u : 0u;
        if (local) atomicAdd(&cnt, local);
        __syncthreads();
        if (cnt >= need) lo = mid; else hi = mid - 1;
        __syncthreads();
    }
    if (threadIdx.x == 0) st.idxT = lo;
}

__global__ void mask_write(float* __restrict__ out) {
    int b = blockIdx.y;
    int idx = blockIdx.x * blockDim.x + threadIdx.x;
    unsigned T = g_sel[b].T;
    unsigned idxT = g_sel[b].idxT;
    unsigned u = fkey(g_W[(size_t)b * SS + idx]);
    float v = (u > T || (u == T && (unsigned)idx >= idxT)) ? 1.0f : 0.0f;
    out[(size_t)b * SS + idx] = v;
}

// ---------------- launcher ----------------
extern "C" void kernel_launch(void* const* d_in, const int* in_sizes, int n_in,
                              void* d_out, int out_size) {
    const float* x = (const float*)d_in[0];
    float* out = (float*)d_out;

    row_stats<<<(BATCH * NTOK) / 8, 256>>>(x);
    pairwise<<<dim3(32, 32, BATCH), 256>>>(x);
    sgemm_nn<<<dim3(8, 8, BATCH), 256>>>(0);
    softmax_rows<<<dim3(NTOK, BATCH), 256>>>();
    sgemm_nn<<<dim3(8, 8, BATCH), 256>>>(1);

    sel_init<<<BATCH, 256>>>();
    for (int level = 0; level < 4; level++) {
        sel_hist<<<dim3(128, BATCH), 256>>>(level);
        sel_scan<<<BATCH, 1>>>(level);
    }
    sel_gather<<<dim3(128, BATCH), 256>>>();
    sel_idx<<<BATCH, 1024>>>();
    mask_write<<<dim3(NTOK, BATCH), 1024>>>(out);
}

// round 5
// speedup vs baseline: 1.3989x; 1.1220x over previous
#include <cuda_runtime.h>
#include <cuda_bf16.h>
#include <math.h>
#include <stdint.h>

#define NTOK 1024
#define CDIM 64
#define BATCH 2
#define SS (NTOK*NTOK)
#define KSEL (SS/6)   /* 174762 */

// ---------------- device scratch (no allocations allowed) ----------------
__device__ float g_mean[BATCH*NTOK];
__device__ float g_std[BATCH*NTOK];
// bf16 3-way splits: e = euclidean (A of gemm1), h = chebyshev (B of gemm1),
// r = corrcoef (B of gemm2), a = attn (A of gemm2)
__device__ __nv_bfloat16 g_e0[BATCH*SS], g_e1[BATCH*SS], g_e2[BATCH*SS];
__device__ __nv_bfloat16 g_h0[BATCH*SS], g_h1[BATCH*SS], g_h2[BATCH*SS];
__device__ __nv_bfloat16 g_r0[BATCH*SS], g_r1[BATCH*SS], g_r2[BATCH*SS];
__device__ __nv_bfloat16 g_a0[BATCH*SS], g_a1[BATCH*SS], g_a2[BATCH*SS];
__device__ float g_L[BATCH*SS];     // logits (gemm1 out, softmax in)
__device__ float g_W[BATCH*SS];     // weighted (gemm2 out)
__device__ unsigned g_hist[BATCH][256];
struct SelState { unsigned prefix, kneed, T, ct, idxT, tiecount; };
__device__ SelState g_sel[BATCH];
__device__ int g_ties[BATCH*SS];

// order-preserving float -> uint key
__device__ __forceinline__ unsigned fkey(float f) {
    unsigned u = __float_as_uint(f);
    return (u & 0x80000000u) ? ~u : (u | 0x80000000u);
}

// 3-way bf16 split: v ~= b0 + b1 + b2 (RN at each stage)
__device__ __forceinline__ void split3(float v, __nv_bfloat16* p0,
                                       __nv_bfloat16* p1, __nv_bfloat16* p2) {
    __nv_bfloat16 b0 = __float2bfloat16(v);
    float r = v - __bfloat162float(b0);
    __nv_bfloat16 b1 = __float2bfloat16(r);
    float r2 = r - __bfloat162float(b1);
    *p0 = b0; *p1 = b1; *p2 = __float2bfloat16(r2);
}

__device__ __forceinline__ uint32_t s2u(const void* p) {
    uint32_t a;
    asm("{ .reg .u64 t; cvta.to.shared.u64 t, %1; cvt.u32.u64 %0, t; }" : "=r"(a) : "l"(p));
    return a;
}

// ---------------- row stats ----------------
__global__ void row_stats(const float* __restrict__ x) {
    int warp = threadIdx.x >> 5, lane = threadIdx.x & 31;
    int row = blockIdx.x * 8 + warp;
    const float* xr = x + (size_t)row * CDIM;
    float v0 = xr[lane], v1 = xr[lane + 32];
    float s = v0 + v1;
    #pragma unroll
    for (int o = 16; o; o >>= 1) s += __shfl_xor_sync(0xFFFFFFFFu, s, o);
    float mean = s * (1.0f / CDIM);
    float d0 = v0 - mean, d1 = v1 - mean;
    float ss = d0 * d0 + d1 * d1;
    #pragma unroll
    for (int o = 16; o; o >>= 1) ss += __shfl_xor_sync(0xFFFFFFFFu, ss, o);
    if (lane == 0) { g_mean[row] = mean; g_std[row] = sqrtf(ss); }
}

// ---------------- fused pairwise -> bf16 splits ----------------
__global__ __launch_bounds__(256) void pairwise(const float* __restrict__ x) {
    __shared__ float xi[32][CDIM + 1];
    __shared__ float xj[32][CDIM + 1];
    __shared__ float smi[32], ssi[32], smj[32], ssj[32];
    int b = blockIdx.z;
    int i0 = blockIdx.y * 32, j0 = blockIdx.x * 32;
    const float* xb = x + (size_t)b * NTOK * CDIM;
    int tid = threadIdx.x;
    for (int l = tid; l < 32 * CDIM; l += 256) {
        int r = l >> 6, c = l & 63;
        xi[r][c] = xb[(size_t)(i0 + r) * CDIM + c];
        xj[r][c] = xb[(size_t)(j0 + r) * CDIM + c];
    }
    if (tid < 32)      { smi[tid] = g_mean[b*NTOK + i0 + tid]; ssi[tid] = g_std[b*NTOK + i0 + tid]; }
    else if (tid < 64) { int t = tid - 32; smj[t] = g_mean[b*NTOK + j0 + t]; ssj[t] = g_std[b*NTOK + j0 + t]; }
    __syncthreads();

    int tx = tid & 15, ty = tid >> 4;
    int r0 = ty * 2, r1 = ty * 2 + 1;
    int c0 = tx, c1 = tx + 16;

    float ssq[2][2] = {{0,0},{0,0}};
    float mx[2][2]  = {{0,0},{0,0}};
    float dt[2][2]  = {{0,0},{0,0}};
    float mi0 = smi[r0], mi1 = smi[r1], mj0 = smj[c0], mj1 = smj[c1];

    #pragma unroll 16
    for (int c = 0; c < CDIM; c++) {
        float a0 = xi[r0][c], a1 = xi[r1][c];
        float b0 = xj[c0][c], b1 = xj[c1][c];
        float ac0 = a0 - mi0, ac1 = a1 - mi1;
        float bc0 = b0 - mj0, bc1 = b1 - mj1;
        float d;
        d = a0 - b0; ssq[0][0] = fmaf(d,d,ssq[0][0]); mx[0][0] = fmaxf(mx[0][0], fabsf(d)); dt[0][0] = fmaf(ac0,bc0,dt[0][0]);
        d = a0 - b1; ssq[0][1] = fmaf(d,d,ssq[0][1]); mx[0][1] = fmaxf(mx[0][1], fabsf(d)); dt[0][1] = fmaf(ac0,bc1,dt[0][1]);
        d = a1 - b0; ssq[1][0] = fmaf(d,d,ssq[1][0]); mx[1][0] = fmaxf(mx[1][0], fabsf(d)); dt[1][0] = fmaf(ac1,bc0,dt[1][0]);
        d = a1 - b1; ssq[1][1] = fmaf(d,d,ssq[1][1]); mx[1][1] = fmaxf(mx[1][1], fabsf(d)); dt[1][1] = fmaf(ac1,bc1,dt[1][1]);
    }
    #pragma unroll
    for (int p = 0; p < 2; p++) {
        int I = i0 + r0 + p;
        float si = ssi[r0 + p];
        #pragma unroll
        for (int q = 0; q < 2; q++) {
            int J = j0 + ((q == 0) ? c0 : c1);
            size_t o = (size_t)b * SS + (size_t)I * NTOK + J;
            split3(sqrtf(ssq[p][q]), g_e0 + o, g_e1 + o, g_e2 + o);
            split3(mx[p][q],         g_h0 + o, g_h1 + o, g_h2 + o);
            float cr = dt[p][q] / (si * ssj[(q==0)?c0:c1]);
            cr = fminf(fmaxf(cr, -1.0f), 1.0f);
            split3(cr, g_r0 + o, g_r1 + o, g_r2 + o);
        }
    }
}

// ---------------- bf16x6 GEMM via mma.sync (HMMA): D = A * B^T ----------------
#define KC 32
#define ROWB 80                 /* padded row: 32 bf16 = 64B data + 16B pad */
#define TILEB (128*ROWB)        /* 10240 */
#define STAGEB (6*TILEB)        /* 61440 */
#define GSMEM (2*STAGEB)        /* 122880 */

#define LDSM4(r, a) \
    asm volatile("ldmatrix.sync.aligned.m8n8.x4.shared.b16 {%0,%1,%2,%3}, [%4];" \
        : "=r"((r)[0]), "=r"((r)[1]), "=r"((r)[2]), "=r"((r)[3]) : "r"(a))

#define MMA16816(d, a, b0r, b1r) \
    asm volatile("mma.sync.aligned.m16n8k16.row.col.f32.bf16.bf16.f32 " \
        "{%0,%1,%2,%3}, {%4,%5,%6,%7}, {%8,%9}, {%0,%1,%2,%3};" \
        : "+f"((d)[0]), "+f"((d)[1]), "+f"((d)[2]), "+f"((d)[3]) \
        : "r"((a)[0]), "r"((a)[1]), "r"((a)[2]), "r"((a)[3]), "r"(b0r), "r"(b1r))

__global__ __launch_bounds__(256, 1) void gemm_mma(int which) {
    extern __shared__ __align__(128) char dsm[];
    uint32_t sb = s2u(dsm);
    int tid = threadIdx.x, lane = tid & 31, wid = tid >> 5;
    int wm = wid >> 2, wn = wid & 3;   // warp tile 64x32, grid 2x4
    size_t boff = (size_t)blockIdx.z * SS;
    const __nv_bfloat16* mats[6];
    if (which == 0) {
        mats[0]=g_e0+boff; mats[1]=g_e1+boff; mats[2]=g_e2+boff;
        mats[3]=g_h0+boff; mats[4]=g_h1+boff; mats[5]=g_h2+boff;
    } else {
        mats[0]=g_a0+boff; mats[1]=g_a1+boff; mats[2]=g_a2+boff;
        mats[3]=g_r0+boff; mats[4]=g_r1+boff; mats[5]=g_r2+boff;
    }
    float* C = (which == 0 ? g_L : g_W) + boff;
    int rowBase = blockIdx.y * 128, colBase = blockIdx.x * 128;

    float acc[4][4][4];
    #pragma unroll
    for (int i = 0; i < 4; i++)
        #pragma unroll
        for (int j = 0; j < 4; j++)
            #pragma unroll
            for (int k = 0; k < 4; k++) acc[i][j][k] = 0.0f;

    // A ldmatrix address components (per thread)
    unsigned aRowOff = (unsigned)(wm*64 + (lane & 15)) * ROWB + ((lane >> 4) << 4);
    // B ldmatrix address components
    unsigned bRowOff = (unsigned)(wn*32 + (lane & 7) + ((lane >> 4) << 3)) * ROWB
                     + (((lane >> 3) & 1) << 4);

#define LOADSTAGE(st, k0) do { \
    unsigned _so = sb + (unsigned)(st)*STAGEB; \
    _Pragma("unroll") \
    for (int i = 0; i < 12; i++) { \
        int g = i * 256 + tid; \
        int mat = g >> 9, idx = g & 511; \
        int row = idx >> 2, c8 = idx & 3; \
        int rb = (mat < 3) ? rowBase : colBase; \
        const __nv_bfloat16* gp = mats[mat] + (size_t)(rb + row) * NTOK + (k0) + c8*8; \
        unsigned sa = _so + mat*TILEB + row*ROWB + c8*16; \
        asm volatile("cp.async.cg.shared.global [%0], [%1], 16;" :: "r"(sa), "l"(gp)); \
    } \
    asm volatile("cp.async.commit_group;"); \
} while(0)

    LOADSTAGE(0, 0);

    const int pa[6] = {0,0,1,0,1,2}, pb[6] = {0,1,0,2,1,0};

    for (int t = 0; t < 32; t++) {
        if (t < 31) {
            LOADSTAGE((t + 1) & 1, (t + 1) * KC);
            asm volatile("cp.async.wait_group 1;");
        } else {
            asm volatile("cp.async.wait_group 0;");
        }
        __syncthreads();
        unsigned stoff = sb + (unsigned)(t & 1) * STAGEB;
        #pragma unroll
        for (int p = 0; p < 6; p++) {
            unsigned abase = stoff + pa[p] * TILEB + aRowOff;
            unsigned bbase = stoff + (3 + pb[p]) * TILEB + bRowOff;
            #pragma unroll
            for (int kf = 0; kf < 2; kf++) {
                uint32_t af[4][4];
                #pragma unroll
                for (int mf = 0; mf < 4; mf++)
                    LDSM4(af[mf], abase + mf * (16 * ROWB) + kf * 32);
                uint32_t bf[4][4];   // bf[np][0..3] -> nblocks 2np,2np+1
                #pragma unroll
                for (int np = 0; np < 2; np++)
                    LDSM4(bf[np], bbase + np * (16 * ROWB) + kf * 32);
                #pragma unroll
                for (int mf = 0; mf < 4; mf++) {
                    MMA16816(acc[mf][0], af[mf], bf[0][0], bf[0][1]);
                    MMA16816(acc[mf][1], af[mf], bf[0][2], bf[0][3]);
                    MMA16816(acc[mf][2], af[mf], bf[1][0], bf[1][1]);
                    MMA16816(acc[mf][3], af[mf], bf[1][2], bf[1][3]);
                }
            }
        }
        __syncthreads();
    }

    // epilogue: D fragment (m16n8) -> gmem
    int r0 = rowBase + wm * 64 + (lane >> 2);
    int c0 = colBase + wn * 32 + (lane & 3) * 2;
    #pragma unroll
    for (int mf = 0; mf < 4; mf++) {
        #pragma unroll
        for (int nb = 0; nb < 4; nb++) {
            float* base = C + (size_t)(r0 + mf * 16) * NTOK + c0 + nb * 8;
            *(float2*)base = make_float2(acc[mf][nb][0], acc[mf][nb][1]);
            *(float2*)(base + 8 * NTOK) = make_float2(acc[mf][nb][2], acc[mf][nb][3]);
        }
    }
#undef LOADSTAGE
}

// ---------------- row softmax of 0.125*L -> attn bf16 splits ----------------
__global__ void softmax_rows() {
    int b = blockIdx.y, row = blockIdx.x;
    size_t base = (size_t)b * SS + (size_t)row * NTOK;
    float* L = g_L + base;
    int tid = threadIdx.x;  // 256
    float v[4];
    #pragma unroll
    for (int i = 0; i < 4; i++) v[i] = L[tid + i * 256] * 0.125f;
    float m = fmaxf(fmaxf(v[0], v[1]), fmaxf(v[2], v[3]));
    __shared__ float red[256];
    red[tid] = m; __syncthreads();
    for (int s = 128; s; s >>= 1) { if (tid < s) red[tid] = fmaxf(red[tid], red[tid + s]); __syncthreads(); }
    m = red[0]; __syncthreads();
    float e[4], sm = 0.0f;
    #pragma unroll
    for (int i = 0; i < 4; i++) { e[i] = expf(v[i] - m); sm += e[i]; }
    red[tid] = sm; __syncthreads();
    for (int s = 128; s; s >>= 1) { if (tid < s) red[tid] += red[tid + s]; __syncthreads(); }
    sm = red[0];
    #pragma unroll
    for (int i = 0; i < 4; i++) {
        size_t o = base + tid + i * 256;
        split3(e[i] / sm, g_a0 + o, g_a1 + o, g_a2 + o);
    }
}

// ---------------- top-k radix select ----------------
__global__ void sel_init() {
    int b = blockIdx.x;
    for (int i = threadIdx.x; i < 256; i += blockDim.x) g_hist[b][i] = 0;
    if (threadIdx.x == 0) {
        g_sel[b].prefix = 0; g_sel[b].kneed = KSEL; g_sel[b].T = 0;
        g_sel[b].ct = 0; g_sel[b].idxT = 0; g_sel[b].tiecount = 0;
    }
}

__global__ void sel_hist(int level) {
    int b = blockIdx.y;
    __shared__ unsigned h[256];
    for (int i = threadIdx.x; i < 256; i += blockDim.x) h[i] = 0;
    __syncthreads();
    unsigned prefix = g_sel[b].prefix;
    int shift = 24 - 8 * level;
    unsigned pmask = (level == 0) ? 0u : (0xFFFFFFFFu << (shift + 8));
    const float* W = g_W + (size_t)b * SS;
    for (int i = blockIdx.x * blockDim.x + threadIdx.x; i < SS; i += gridDim.x * blockDim.x) {
        unsigned u = fkey(W[i]);
        if ((u & pmask) == prefix) atomicAdd(&h[(u >> shift) & 255], 1u);
    }
    __syncthreads();
    for (int i = threadIdx.x; i < 256; i += blockDim.x)
        if (h[i]) atomicAdd(&g_hist[b][i], h[i]);
}

__global__ void sel_scan(int level) {
    int b = blockIdx.x;
    SelState& st = g_sel[b];
    int shift = 24 - 8 * level;
    unsigned kneed = st.kneed;
    int sel = 0; unsigned cnt = 0;
    for (int bin = 255; bin >= 0; bin--) {
        unsigned c = g_hist[b][bin];
        if (kneed <= c) { sel = bin; cnt = c; break; }
        kneed -= c;
    }
    st.prefix |= ((unsigned)sel) << shift;
    st.kneed = kneed;
    if (level == 3) { st.T = st.prefix; st.ct = cnt; }
    for (int i = 0; i < 256; i++) g_hist[b][i] = 0;
}

__global__ void sel_gather() {
    int b = blockIdx.y;
    unsigned T = g_sel[b].T;
    const float* W = g_W + (size_t)b * SS;
    for (int i = blockIdx.x * blockDim.x + threadIdx.x; i < SS; i += gridDim.x * blockDim.x) {
        if (fkey(W[i]) == T) {
            unsigned pos = atomicAdd(&g_sel[b].tiecount, 1u);
            g_ties[(size_t)b * SS + pos] = i;
        }
    }
}

__global__ void sel_idx() {
    int b = blockIdx.x;
    __shared__ unsigned cnt;
    SelState& st = g_sel[b];
    unsigned ct = st.ct, need = st.kneed;
    if (need >= ct) { if (threadIdx.x == 0) st.idxT = 0; return; }
    const int* ties = g_ties + (size_t)b * SS;
    unsigned lo = 0, hi = SS - 1;
    for (int iter = 0; iter < 22; iter++) {
        if (lo >= hi) break;
        unsigned mid = (lo + hi + 1u) >> 1;
        if (threadIdx.x == 0) cnt = 0;
        __syncthreads();
        unsigned local = 0;
        for (unsigned i = threadIdx.x; i < ct; i += blockDim.x)
            local += (ties[i] >= (int)mid) ? 1u : 0u;
        if (local) atomicAdd(&cnt, local);
        __syncthreads();
        if (cnt >= need) lo = mid; else hi = mid - 1;
        __syncthreads();
    }
    if (threadIdx.x == 0) st.idxT = lo;
}

__global__ void mask_write(float* __restrict__ out) {
    int b = blockIdx.y;
    int idx = blockIdx.x * blockDim.x + threadIdx.x;
    unsigned T = g_sel[b].T;
    unsigned idxT = g_sel[b].idxT;
    unsigned u = fkey(g_W[(size_t)b * SS + idx]);
    float v = (u > T || (u == T && (unsigned)idx >= idxT)) ? 1.0f : 0.0f;
    out[(size_t)b * SS + idx] = v;
}

// ---------------- launcher ----------------
extern "C" void kernel_launch(void* const* d_in, const int* in_sizes, int n_in,
                              void* d_out, int out_size) {
    const float* x = (const float*)d_in[0];
    float* out = (float*)d_out;

    cudaFuncSetAttribute(gemm_mma, cudaFuncAttributeMaxDynamicSharedMemorySize, GSMEM);

    row_stats<<<(BATCH * NTOK) / 8, 256>>>(x);
    pairwise<<<dim3(32, 32, BATCH), 256>>>(x);
    gemm_mma<<<dim3(8, 8, BATCH), 256, GSMEM>>>(0);
    softmax_rows<<<dim3(NTOK, BATCH), 256>>>();
    gemm_mma<<<dim3(8, 8, BATCH), 256, GSMEM>>>(1);

    sel_init<<<BATCH, 256>>>();
    for (int level = 0; level < 4; level++) {
        sel_hist<<<dim3(128, BATCH), 256>>>(level);
        sel_scan<<<BATCH, 1>>>(level);
    }
    sel_gather<<<dim3(128, BATCH), 256>>>();
    sel_idx<<<BATCH, 1024>>>();
    mask_write<<<dim3(NTOK, BATCH), 1024>>>(out);
}